// round 8
// baseline (speedup 1.0000x reference)
#include <cuda_runtime.h>
#include <math.h>

#define D_ 128
#define NMAX 50016
#define EPMAX 550032
#define MAXN 0.99999f
#define MINNORM 1e-15f

// ---------------- scratch ----------------
__device__ float g_xe[NMAX * D_];
__device__ float g_xh[NMAX * D_];
__device__ float g_lx[NMAX * D_];
__device__ float g_ai[NMAX * 4];
__device__ float g_aj[NMAX * 4];
__device__ float g_hi[NMAX * 4];
__device__ float g_hj[NMAX * 4];
__device__ float g_x2[NMAX];
__device__ float g_de[EPMAX];       // exp(distance)
__device__ float g_WtE[D_ * D_];
__device__ float g_WtH[D_ * D_];
__device__ int   g_deg[NMAX];
__device__ int   g_cur[NMAX];
__device__ int   g_start[NMAX + 1];
__device__ int   g_csrc[EPMAX];
__device__ int   g_bsum[256];

// ---------------- helpers ----------------
__device__ __forceinline__ float atanhc(float x) {
    x = fminf(fmaxf(x, -1.0f + 1e-7f), 1.0f - 1e-7f);
    return atanhf(x);
}
__device__ __forceinline__ float wsum(float v) {
#pragma unroll
    for (int o = 16; o; o >>= 1) v += __shfl_xor_sync(0xffffffffu, v, o);
    return v;
}
__device__ __forceinline__ float d4(float4 a, float4 b) {
    return a.x * b.x + a.y * b.y + a.z * b.z + a.w * b.w;
}
__device__ __forceinline__ float4 f4s(float4 a, float s) {
    return make_float4(a.x * s, a.y * s, a.z * s, a.w * s);
}
__device__ __forceinline__ float4 f4axby(float a, float4 x, float b, float4 y) {
    return make_float4(a * x.x + b * y.x, a * x.y + b * y.y,
                       a * x.z + b * y.z, a * x.w + b * y.w);
}
__device__ __forceinline__ float lrelu(float v) { return v >= 0.f ? v : 0.2f * v; }

// packed f32x2 helpers (Blackwell FFMA2)
__device__ __forceinline__ void ffma2(unsigned long long &acc,
                                      unsigned long long a, unsigned long long b) {
    asm("fma.rn.f32x2 %0, %1, %2, %3;" : "=l"(acc) : "l"(a), "l"(b), "l"(acc));
}
__device__ __forceinline__ unsigned long long pack2(float s) {
    unsigned u = __float_as_uint(s);
    unsigned long long r;
    asm("mov.b64 %0, {%1, %1};" : "=l"(r) : "r"(u));
    return r;
}
__device__ __forceinline__ float4 unpack4(unsigned long long lo, unsigned long long hi) {
    float4 v;
    asm("mov.b64 {%0, %1}, %2;" : "=f"(v.x), "=f"(v.y) : "l"(lo));
    asm("mov.b64 {%0, %1}, %2;" : "=f"(v.z), "=f"(v.w) : "l"(hi));
    return v;
}

// ---------------- init: zero degrees + transpose weights ----------------
__global__ __launch_bounds__(256) void init_kernel(const float* __restrict__ We,
                                                   const float* __restrict__ Wh, int N) {
    int i = blockIdx.x * blockDim.x + threadIdx.x;
    if (i < N) g_deg[i] = 0;
    if (i < 2 * D_ * D_) {
        int m = i >> 14;
        int k = (i >> 7) & 127;
        int c = i & 127;
        if (m == 0) g_WtE[k * D_ + c] = We[c * D_ + k];
        else        g_WtH[k * D_ + c] = Wh[c * D_ + k];
    }
}

__global__ __launch_bounds__(256) void count_kernel(const int* __restrict__ ei, int E, int EP) {
    int e = blockIdx.x * blockDim.x + threadIdx.x;
    if (e >= EP) return;
    int dn = (e < E) ? ei[E + e] : (e - E);
    atomicAdd(&g_deg[dn], 1);
}

__global__ __launch_bounds__(256) void scan1_kernel(int N) {
    __shared__ int sm[256];
    int i = blockIdx.x * 256 + threadIdx.x;
    int v = (i < N) ? g_deg[i] : 0;
    sm[threadIdx.x] = v;
    __syncthreads();
#pragma unroll
    for (int d = 1; d < 256; d <<= 1) {
        int t = (threadIdx.x >= d) ? sm[threadIdx.x - d] : 0;
        __syncthreads();
        sm[threadIdx.x] += t;
        __syncthreads();
    }
    if (i < N) g_start[i] = sm[threadIdx.x] - v;
    if (threadIdx.x == 255) g_bsum[blockIdx.x] = sm[255];
}

__global__ __launch_bounds__(256) void scan2_kernel(int nb) {
    __shared__ int sm[256];
    int v = (threadIdx.x < nb) ? g_bsum[threadIdx.x] : 0;
    sm[threadIdx.x] = v;
    __syncthreads();
#pragma unroll
    for (int d = 1; d < 256; d <<= 1) {
        int t = (threadIdx.x >= d) ? sm[threadIdx.x - d] : 0;
        __syncthreads();
        sm[threadIdx.x] += t;
        __syncthreads();
    }
    g_bsum[threadIdx.x] = sm[threadIdx.x] - v;
}

__global__ __launch_bounds__(256) void scan3_kernel(int N, int EP) {
    int i = blockIdx.x * 256 + threadIdx.x;
    if (i < N) { g_start[i] += g_bsum[i >> 8]; g_cur[i] = 0; }
    if (i == 0) g_start[N] = EP;
}

__global__ __launch_bounds__(256) void scatter_kernel(const int* __restrict__ ei, int E, int EP) {
    int e = blockIdx.x * blockDim.x + threadIdx.x;
    if (e >= EP) return;
    int s, dn;
    if (e < E) { s = ei[e]; dn = ei[E + e]; } else { s = dn = e - E; }
    int pos = atomicAdd(&g_cur[dn], 1);
    g_csrc[g_start[dn] + pos] = s;
}

// ---------------- node bodies (8 nodes/warp) ----------------
__device__ __forceinline__ void node_e_body(float (*sx)[D_],
                                            const float* __restrict__ x,
                                            const float* __restrict__ b_lin,
                                            const float* __restrict__ att,
                                            int N, int base, int l) {
#pragma unroll
    for (int j = 0; j < 8; j++) {
        int n = min(base + j, N - 1);
        ((float4*)sx[j])[l] = ((const float4*)x)[n * 32 + l];
    }
    __syncwarp();
    unsigned long long acc[8][2];
#pragma unroll
    for (int j = 0; j < 8; j++) { acc[j][0] = 0ull; acc[j][1] = 0ull; }
    const ulonglong2* Wt = (const ulonglong2*)g_WtE;
#pragma unroll 2
    for (int k = 0; k < D_; k++) {
        ulonglong2 wv = Wt[k * 32 + l];
#pragma unroll
        for (int j = 0; j < 8; j++) {
            unsigned long long ss = pack2(sx[j][k]);
            ffma2(acc[j][0], ss, wv.x);
            ffma2(acc[j][1], ss, wv.y);
        }
    }
    float4 bv = ((const float4*)b_lin)[l];
    int h = l >> 3, j0 = (l & 7) * 4;
    const float* at  = att + h * 64 + j0;
    const float* at2 = at + 32;
#pragma unroll
    for (int j = 0; j < 8; j++) {
        int n = base + j;
        if (n >= N) break;
        float4 a = unpack4(acc[j][0], acc[j][1]);
        a.x += bv.x; a.y += bv.y; a.z += bv.z; a.w += bv.w;
        ((float4*)g_xe)[n * 32 + l] = a;
        float pi = a.x * at[0]  + a.y * at[1]  + a.z * at[2]  + a.w * at[3];
        float pj = a.x * at2[0] + a.y * at2[1] + a.z * at2[2] + a.w * at2[3];
#pragma unroll
        for (int o = 4; o; o >>= 1) {
            pi += __shfl_down_sync(0xffffffffu, pi, o, 8);
            pj += __shfl_down_sync(0xffffffffu, pj, o, 8);
        }
        if ((l & 7) == 0) { g_ai[n * 4 + h] = pi; g_aj[n * 4 + h] = pj; }
    }
}

__device__ __forceinline__ void node_h_body(float (*sx)[D_],
                                            const float* __restrict__ x,
                                            const float* __restrict__ b_lin,
                                            const float* __restrict__ att,
                                            int N, int base, int l) {
    float pnx[8];
#pragma unroll
    for (int j = 0; j < 8; j++) {
        int n = min(base + j, N - 1);
        float4 xv = ((const float4*)x)[n * 32 + l];
        ((float4*)sx[j])[l] = xv;
        pnx[j] = d4(xv, xv);
    }
#pragma unroll
    for (int o = 16; o; o >>= 1) {
#pragma unroll
        for (int j = 0; j < 8; j++) pnx[j] += __shfl_xor_sync(0xffffffffu, pnx[j], o);
    }
    __syncwarp();
    unsigned long long acc[8][2];
#pragma unroll
    for (int j = 0; j < 8; j++) { acc[j][0] = 0ull; acc[j][1] = 0ull; }
    const ulonglong2* Wt = (const ulonglong2*)g_WtH;
#pragma unroll 2
    for (int k = 0; k < D_; k++) {
        ulonglong2 wv = Wt[k * 32 + l];
#pragma unroll
        for (int j = 0; j < 8; j++) {
            unsigned long long ss = pack2(sx[j][k]);
            ffma2(acc[j][0], ss, wv.x);
            ffma2(acc[j][1], ss, wv.y);
        }
    }
    float4 bvv = ((const float4*)b_lin)[l];
    float nb = fmaxf(sqrtf(wsum(d4(bvv, bvv))), MINNORM);
    float nhb = fminf(tanhf(nb), MAXN);
    float4 hb = f4s(bvv, nhb / nb);
    float y2 = nhb * nhb;

    float4 mx[8];
    float pm[8];
#pragma unroll
    for (int j = 0; j < 8; j++) {
        mx[j] = unpack4(acc[j][0], acc[j][1]);
        pm[j] = d4(mx[j], mx[j]);
    }
#pragma unroll
    for (int o = 16; o; o >>= 1) {
#pragma unroll
        for (int j = 0; j < 8; j++) pm[j] += __shfl_xor_sync(0xffffffffu, pm[j], o);
    }
    float nmv[8];
#pragma unroll
    for (int j = 0; j < 8; j++) {
        float n_x = fmaxf(sqrtf(pnx[j]), MINNORM);
        float n_mx = fmaxf(sqrtf(pm[j]), MINNORM);
        nmv[j] = fminf(tanhf(n_mx / n_x * atanhc(n_x)), MAXN);
        float s = nmv[j] / n_mx;
        mx[j] = f4s(mx[j], s);
    }
    float pxy[8];
#pragma unroll
    for (int j = 0; j < 8; j++) pxy[j] = d4(mx[j], hb);
#pragma unroll
    for (int o = 16; o; o >>= 1) {
#pragma unroll
        for (int j = 0; j < 8; j++) pxy[j] += __shfl_xor_sync(0xffffffffu, pxy[j], o);
    }

    int h = l >> 3, j0 = (l & 7) * 4;
    const float* at  = att + h * 64 + j0;
    const float* at2 = at + 32;
#pragma unroll
    for (int j = 0; j < 8; j++) {
        int n = base + j;
        if (n >= N) break;
        float x2 = nmv[j] * nmv[j];
        float xy = pxy[j];
        float A = 1.f + 2.f * xy + y2, B = 1.f - x2;
        float den = fmaxf(1.f + 2.f * xy + x2 * y2, MINNORM);
        float invden = 1.f / den;
        float nxh2 = fmaxf(A * A * x2 + 2.f * A * B * xy + B * B * y2, 0.f)
                     * invden * invden;
        float nxh = fmaxf(sqrtf(nxh2), MINNORM);
        float c = (nxh > MAXN) ? (MAXN / nxh) : 1.f;
        float4 xh = f4s(f4axby(A, mx[j], B, hb), invden * c);
        float nfin = c * nxh;
        float x2f = nfin * nfin;
        ((float4*)g_xh)[n * 32 + l] = xh;
        if (l == 0) g_x2[n] = x2f;
        float ncl = fmaxf(nfin, MINNORM);
        float4 lx = f4s(xh, atanhc(ncl) / ncl);
        ((float4*)g_lx)[n * 32 + l] = lx;
        float pi = lx.x * at[0]  + lx.y * at[1]  + lx.z * at[2]  + lx.w * at[3];
        float pj = lx.x * at2[0] + lx.y * at2[1] + lx.z * at2[2] + lx.w * at2[3];
#pragma unroll
        for (int o = 4; o; o >>= 1) {
            pi += __shfl_down_sync(0xffffffffu, pi, o, 8);
            pj += __shfl_down_sync(0xffffffffu, pj, o, 8);
        }
        if ((l & 7) == 0) { g_hi[n * 4 + h] = pi; g_hj[n * 4 + h] = pj; }
    }
}

// unified node kernel: first ngrp blocks euclid, next ngrp blocks hyperbolic
__global__ __launch_bounds__(128) void node_both_kernel(const float* __restrict__ x_e,
                                                        const float* __restrict__ x_h,
                                                        const float* __restrict__ ble,
                                                        const float* __restrict__ blh,
                                                        const float* __restrict__ ae,
                                                        const float* __restrict__ ah,
                                                        int N, int ngrp) {
    __shared__ float sx[4][8][D_];
    int w = threadIdx.x >> 5, l = threadIdx.x & 31;
    int b = blockIdx.x;
    if (b < ngrp) {
        int base = b * 32 + w * 8;
        if (base < N) node_e_body(sx[w], x_e, ble, ae, N, base, l);
    } else {
        int base = (b - ngrp) * 32 + w * 8;
        if (base < N) node_h_body(sx[w], x_h, blh, ah, N, base, l);
    }
}

// ---------------- fused edge + finalize (8-lane-group dot) ----------------
__global__ __launch_bounds__(256) void fused_edge_kernel(const float* __restrict__ b_e,
                                                         const float* __restrict__ b_h,
                                                         const float* __restrict__ att_hf,
                                                         const float* __restrict__ att_ef,
                                                         float* __restrict__ out, int N) {
    int w = (blockIdx.x * blockDim.x + threadIdx.x) >> 5;
    int l = threadIdx.x & 31;
    if (w >= N) return;
    int dn = w;
    int beg = g_start[dn], end = g_start[dn + 1];
    int h = l >> 3;
    int gi = l >> 3, li = l & 7;
    bool leader = (li == 0);

    float  x2d = g_x2[dn];
    float  ai_l = g_ai[dn * 4 + h];
    float  hi_l = g_hi[dn * 4 + h];
    // dst vector chunks for 8-lane-group dot (lane li owns float4s li, li+8, li+16, li+24)
    const float4* xdp = (const float4*)g_xh + dn * 32;
    float4 xdg0 = xdp[li], xdg1 = xdp[li + 8], xdg2 = xdp[li + 16], xdg3 = xdp[li + 24];

    // ---- Pass A: distances (group dot) + euclid aggregation (masked x4) ----
    float sum_d = 0.f, sum_e = 0.f;
    float4 acc_e = make_float4(0.f, 0.f, 0.f, 0.f);
    for (int k = beg; k < end; k += 4) {
        int k1 = min(k + 1, end - 1), k2 = min(k + 2, end - 1), k3 = min(k + 3, end - 1);
        float m1 = (k + 1 < end) ? 1.f : 0.f;
        float m2 = (k + 2 < end) ? 1.f : 0.f;
        float m3 = (k + 3 < end) ? 1.f : 0.f;
        int s0 = g_csrc[k], s1 = g_csrc[k1], s2 = g_csrc[k2], s3 = g_csrc[k3];
        // euclid aggregation: all lanes, 4 edges
        float4 e0 = ((const float4*)g_xe)[s0 * 32 + l];
        float4 e1 = ((const float4*)g_xe)[s1 * 32 + l];
        float4 e2 = ((const float4*)g_xe)[s2 * 32 + l];
        float4 e3 = ((const float4*)g_xe)[s3 * 32 + l];
        float le0 = expf(lrelu(ai_l + g_aj[s0 * 4 + h]));
        float le1 = expf(lrelu(ai_l + g_aj[s1 * 4 + h])) * m1;
        float le2 = expf(lrelu(ai_l + g_aj[s2 * 4 + h])) * m2;
        float le3 = expf(lrelu(ai_l + g_aj[s3 * 4 + h])) * m3;
        acc_e.x = fmaf(le0, e0.x, fmaf(le1, e1.x, fmaf(le2, e2.x, fmaf(le3, e3.x, acc_e.x))));
        acc_e.y = fmaf(le0, e0.y, fmaf(le1, e1.y, fmaf(le2, e2.y, fmaf(le3, e3.y, acc_e.y))));
        acc_e.z = fmaf(le0, e0.z, fmaf(le1, e1.z, fmaf(le2, e2.z, fmaf(le3, e3.z, acc_e.z))));
        acc_e.w = fmaf(le0, e0.w, fmaf(le1, e1.w, fmaf(le2, e2.w, fmaf(le3, e3.w, acc_e.w))));
        if (l == 0) sum_e += le0 + le1 + le2 + le3;   // head sums identical across heads? no:
        // NOTE: sums are per-head; each 8-lane group leader keeps its head's sum
        if (li == 0 && l != 0) sum_e += le0 + le1 + le2 + le3;
        // group dot: group gi handles edge k+gi
        int sg = (gi == 0) ? s0 : (gi == 1) ? s1 : (gi == 2) ? s2 : s3;
        const float4* xs = (const float4*)g_xh + sg * 32;
        float p = d4(xdg0, xs[li]) + d4(xdg1, xs[li + 8])
                + d4(xdg2, xs[li + 16]) + d4(xdg3, xs[li + 24]);
        p += __shfl_xor_sync(0xffffffffu, p, 4);
        p += __shfl_xor_sync(0xffffffffu, p, 2);
        p += __shfl_xor_sync(0xffffffffu, p, 1);
        if (li == 0 && k + gi < end) {
            float yy = g_x2[sg];
            float A = 1.f - 2.f * p + yy, B = 1.f - x2d;
            float den = fmaxf(1.f - 2.f * p + x2d * yy, MINNORM);
            float num2 = fmaxf(A * A * x2d + B * B * yy - 2.f * A * B * p, 0.f);
            float edd = expf(2.f * atanhc(sqrtf(num2) / den));
            g_de[k + gi] = edd;
            sum_d += edd;
        }
    }
    float inv_sd = 1.f / (wsum(sum_d) + 1e-16f);

    // ---- Pass B: hyperbolic aggregation (masked x4) ----
    float sum_h = 0.f;
    float4 acc_h = make_float4(0.f, 0.f, 0.f, 0.f);
    for (int k = beg; k < end; k += 4) {
        int k1 = min(k + 1, end - 1), k2 = min(k + 2, end - 1), k3 = min(k + 3, end - 1);
        float m1 = (k + 1 < end) ? 1.f : 0.f;
        float m2 = (k + 2 < end) ? 1.f : 0.f;
        float m3 = (k + 3 < end) ? 1.f : 0.f;
        int s0 = g_csrc[k], s1 = g_csrc[k1], s2 = g_csrc[k2], s3 = g_csrc[k3];
        float4 l0 = ((const float4*)g_lx)[s0 * 32 + l];
        float4 l1 = ((const float4*)g_lx)[s1 * 32 + l];
        float4 l2 = ((const float4*)g_lx)[s2 * 32 + l];
        float4 l3 = ((const float4*)g_lx)[s3 * 32 + l];
        float d0 = g_de[k] * inv_sd,  d1 = g_de[k1] * inv_sd;
        float d2 = g_de[k2] * inv_sd, d3 = g_de[k3] * inv_sd;
        float a0 = expf(lrelu((hi_l + g_hj[s0 * 4 + h]) * d0));
        float a1 = expf(lrelu((hi_l + g_hj[s1 * 4 + h]) * d1)) * m1;
        float a2 = expf(lrelu((hi_l + g_hj[s2 * 4 + h]) * d2)) * m2;
        float a3 = expf(lrelu((hi_l + g_hj[s3 * 4 + h]) * d3)) * m3;
        acc_h.x = fmaf(a0, l0.x, fmaf(a1, l1.x, fmaf(a2, l2.x, fmaf(a3, l3.x, acc_h.x))));
        acc_h.y = fmaf(a0, l0.y, fmaf(a1, l1.y, fmaf(a2, l2.y, fmaf(a3, l3.y, acc_h.y))));
        acc_h.z = fmaf(a0, l0.z, fmaf(a1, l1.z, fmaf(a2, l2.z, fmaf(a3, l3.z, acc_h.z))));
        acc_h.w = fmaf(a0, l0.w, fmaf(a1, l1.w, fmaf(a2, l2.w, fmaf(a3, l3.w, acc_h.w))));
        if (li == 0) sum_h += a0 + a1 + a2 + a3;
    }

    float se = __shfl_sync(0xffffffffu, sum_e, h << 3);
    float sh = __shfl_sync(0xffffffffu, sum_h, h << 3);
    float inv_se = 1.f / (se + 1e-16f);
    float inv_sh = 1.f / (sh + 1e-16f);

    // ---- Finalize (scalar-norm algebra; 3 warp reductions) ----
    int n = dn;
    float4 be = ((const float4*)b_e)[l];
    float4 eo = make_float4(fmaxf(fmaf(acc_e.x, inv_se, be.x), 0.f),
                            fmaxf(fmaf(acc_e.y, inv_se, be.y), 0.f),
                            fmaxf(fmaf(acc_e.z, inv_se, be.z), 0.f),
                            fmaxf(fmaf(acc_e.w, inv_se, be.w), 0.f));
    float4 bh = ((const float4*)b_h)[l];
    float4 ot = make_float4(fmaxf(fmaf(acc_h.x, inv_sh, bh.x), 0.f),
                            fmaxf(fmaf(acc_h.y, inv_sh, bh.y), 0.f),
                            fmaxf(fmaf(acc_h.z, inv_sh, bh.z), 0.f),
                            fmaxf(fmaf(acc_h.w, inv_sh, bh.w), 0.f));
    float nt = fmaxf(sqrtf(wsum(d4(ot, ot))), MINNORM);
    float nho = fminf(tanhf(nt), MAXN);
    float4 ho = f4s(ot, nho / nt);
    float x2 = nho * nho;
    float ne2 = wsum(d4(eo, eo));
    float ne = fmaxf(sqrtf(ne2), MINNORM);
    float nye = fminf(tanhf(ne), MAXN);
    float4 ye = f4s(eo, nye / ne);
    float y2 = nye * nye;
    float xy = wsum(d4(ho, ye));
    float A = 1.f - 2.f * xy + y2, B = 1.f - x2;
    float den = fmaxf(1.f - 2.f * xy + x2 * y2, MINNORM);
    float num2 = fmaxf(A * A * x2 + B * B * y2 - 2.f * A * B * xy, 0.f);
    float r = 2.f * atanhc(sqrtf(num2) / den) * att_hf[0];
    float ny = fmaxf(nye, MINNORM);
    float t3 = tanhf(r * atanhc(ny));
    float kxe = t3 / ny;
    float nxe2 = fabsf(kxe) * nye;
    float c2 = (nxe2 > MAXN) ? (MAXN / fmaxf(nxe2, MINNORM)) : 1.f;
    float kxe2 = kxe * c2;
    float4 xe2 = f4s(ye, kxe2);
    float nxe2c = nxe2 * c2;
    float y2b = nxe2c * nxe2c;
    float xyb = xy * kxe2;
    float A2 = 1.f + 2.f * xyb + y2b, B2 = 1.f - x2;
    float den2 = fmaxf(1.f + 2.f * xyb + x2 * y2b, MINNORM);
    float invden2 = 1.f / den2;
    float nhf2 = fmaxf(A2 * A2 * x2 + 2.f * A2 * B2 * xyb + B2 * B2 * y2b, 0.f)
                 * invden2 * invden2;
    float nhf = fmaxf(sqrtf(nhf2), MINNORM);
    float c3 = (nhf > MAXN) ? (MAXN / nhf) : 1.f;
    float4 hf = f4s(f4axby(A2, ho, B2, xe2), invden2 * c3);
    float nclh = fmaxf(nho, MINNORM);
    float alh = atanhc(nclh);
    float kl = alh / nclh;
    float4 lh = f4s(ho, kl);
    float dot_ho_eo = xy * ne / nye;
    float de = (alh * alh - 2.f * kl * dot_ho_eo + ne2) * att_ef[0];
    float4 ef = make_float4(eo.x + de * lh.x, eo.y + de * lh.y,
                            eo.z + de * lh.z, eo.w + de * lh.w);
    ((float4*)out)[n * 32 + l] = hf;
    ((float4*)out)[(size_t)N * 32 + n * 32 + l] = ef;
}

// ---------------- launch ----------------
extern "C" void kernel_launch(void* const* d_in, const int* in_sizes, int n_in,
                              void* d_out, int out_size) {
    const float* x_e      = (const float*)d_in[0];
    const float* x_h      = (const float*)d_in[1];
    const int*   ei       = (const int*)d_in[2];
    const float* W_e      = (const float*)d_in[3];
    const float* b_lin_e  = (const float*)d_in[4];
    const float* att_e    = (const float*)d_in[5];
    const float* b_e      = (const float*)d_in[6];
    const float* W_h      = (const float*)d_in[7];
    const float* b_lin_h  = (const float*)d_in[8];
    const float* att_h    = (const float*)d_in[9];
    const float* b_h      = (const float*)d_in[10];
    const float* att_hf   = (const float*)d_in[11];
    const float* att_ef   = (const float*)d_in[12];
    float* out = (float*)d_out;

    int N  = in_sizes[0] / D_;
    int E  = in_sizes[2] / 2;
    int EP = E + N;
    int nsb = (N + 255) / 256;
    int ngrp = (N + 31) / 32;
    int ninit = (N > 2 * D_ * D_) ? N : 2 * D_ * D_;

    static cudaStream_t s2 = nullptr;
    static cudaEvent_t evFork = nullptr, evJoin2 = nullptr;
    if (s2 == nullptr) {
        cudaStreamCreateWithFlags(&s2, cudaStreamNonBlocking);
        cudaEventCreateWithFlags(&evFork, cudaEventDisableTiming);
        cudaEventCreateWithFlags(&evJoin2, cudaEventDisableTiming);
    }

    // main stream: init (weights + deg zero)
    init_kernel<<<(ninit + 255) / 256, 256>>>(W_e, W_h, N);
    cudaEventRecord(evFork, 0);

    // side stream s2: CSR build chain
    cudaStreamWaitEvent(s2, evFork, 0);
    count_kernel<<<(EP + 255) / 256, 256, 0, s2>>>(ei, E, EP);
    scan1_kernel<<<nsb, 256, 0, s2>>>(N);
    scan2_kernel<<<1, 256, 0, s2>>>(nsb);
    scan3_kernel<<<(N + 255) / 256, 256, 0, s2>>>(N, EP);
    scatter_kernel<<<(EP + 255) / 256, 256, 0, s2>>>(ei, E, EP);
    cudaEventRecord(evJoin2, s2);

    // main stream: both node branches in one launch (co-resident)
    node_both_kernel<<<2 * ngrp, 128>>>(x_e, x_h, b_lin_e, b_lin_h, att_e, att_h, N, ngrp);

    // join, then fused edge + finalize
    cudaStreamWaitEvent(0, evJoin2, 0);
    fused_edge_kernel<<<(N * 32 + 255) / 256, 256>>>(b_e, b_h, att_hf, att_ef, out, N);
}

// round 10
// speedup vs baseline: 1.5100x; 1.5100x over previous
#include <cuda_runtime.h>
#include <math.h>

#define D_ 128
#define NMAX 50016
#define EPMAX 550032
#define MAXN 0.99999f
#define MINNORM 1e-15f

// ---------------- scratch ----------------
__device__ float g_xe[NMAX * D_];
__device__ float g_xh[NMAX * D_];
__device__ float g_lx[NMAX * D_];
__device__ float g_ai[NMAX * 4];
__device__ float g_aj[NMAX * 4];
__device__ float g_hi[NMAX * 4];
__device__ float g_hj[NMAX * 4];
__device__ float g_x2[NMAX];
__device__ float g_de[EPMAX];       // exp(distance)
__device__ float g_WtE[D_ * D_];
__device__ float g_WtH[D_ * D_];
__device__ int   g_deg[NMAX];
__device__ int   g_cur[NMAX];
__device__ int   g_start[NMAX + 1];
__device__ int   g_csrc[EPMAX];
__device__ int   g_bsum[256];

// ---------------- helpers ----------------
__device__ __forceinline__ float atanhc(float x) {
    x = fminf(fmaxf(x, -1.0f + 1e-7f), 1.0f - 1e-7f);
    return atanhf(x);
}
__device__ __forceinline__ float wsum(float v) {
#pragma unroll
    for (int o = 16; o; o >>= 1) v += __shfl_xor_sync(0xffffffffu, v, o);
    return v;
}
__device__ __forceinline__ float d4(float4 a, float4 b) {
    return a.x * b.x + a.y * b.y + a.z * b.z + a.w * b.w;
}
__device__ __forceinline__ float4 f4s(float4 a, float s) {
    return make_float4(a.x * s, a.y * s, a.z * s, a.w * s);
}
__device__ __forceinline__ float4 f4axby(float a, float4 x, float b, float4 y) {
    return make_float4(a * x.x + b * y.x, a * x.y + b * y.y,
                       a * x.z + b * y.z, a * x.w + b * y.w);
}
__device__ __forceinline__ float lrelu(float v) { return v >= 0.f ? v : 0.2f * v; }

// packed f32x2 helpers (Blackwell FFMA2)
__device__ __forceinline__ void ffma2(unsigned long long &acc,
                                      unsigned long long a, unsigned long long b) {
    asm("fma.rn.f32x2 %0, %1, %2, %3;" : "=l"(acc) : "l"(a), "l"(b), "l"(acc));
}
__device__ __forceinline__ unsigned long long pack2(float s) {
    unsigned u = __float_as_uint(s);
    unsigned long long r;
    asm("mov.b64 %0, {%1, %1};" : "=l"(r) : "r"(u));
    return r;
}
__device__ __forceinline__ float4 unpack4(unsigned long long lo, unsigned long long hi) {
    float4 v;
    asm("mov.b64 {%0, %1}, %2;" : "=f"(v.x), "=f"(v.y) : "l"(lo));
    asm("mov.b64 {%0, %1}, %2;" : "=f"(v.z), "=f"(v.w) : "l"(hi));
    return v;
}

// ---------------- init: zero degrees + transpose weights ----------------
__global__ __launch_bounds__(256) void init_kernel(const float* __restrict__ We,
                                                   const float* __restrict__ Wh, int N) {
    int i = blockIdx.x * blockDim.x + threadIdx.x;
    if (i < N) g_deg[i] = 0;
    if (i < 2 * D_ * D_) {
        int m = i >> 14;
        int k = (i >> 7) & 127;
        int c = i & 127;
        if (m == 0) g_WtE[k * D_ + c] = We[c * D_ + k];
        else        g_WtH[k * D_ + c] = Wh[c * D_ + k];
    }
}

__global__ __launch_bounds__(256) void count_kernel(const int* __restrict__ ei, int E, int EP) {
    int e = blockIdx.x * blockDim.x + threadIdx.x;
    if (e >= EP) return;
    int dn = (e < E) ? ei[E + e] : (e - E);
    atomicAdd(&g_deg[dn], 1);
}

__global__ __launch_bounds__(256) void scan1_kernel(int N) {
    __shared__ int sm[256];
    int i = blockIdx.x * 256 + threadIdx.x;
    int v = (i < N) ? g_deg[i] : 0;
    sm[threadIdx.x] = v;
    __syncthreads();
#pragma unroll
    for (int d = 1; d < 256; d <<= 1) {
        int t = (threadIdx.x >= d) ? sm[threadIdx.x - d] : 0;
        __syncthreads();
        sm[threadIdx.x] += t;
        __syncthreads();
    }
    if (i < N) g_start[i] = sm[threadIdx.x] - v;
    if (threadIdx.x == 255) g_bsum[blockIdx.x] = sm[255];
}

__global__ __launch_bounds__(256) void scan2_kernel(int nb) {
    __shared__ int sm[256];
    int v = (threadIdx.x < nb) ? g_bsum[threadIdx.x] : 0;
    sm[threadIdx.x] = v;
    __syncthreads();
#pragma unroll
    for (int d = 1; d < 256; d <<= 1) {
        int t = (threadIdx.x >= d) ? sm[threadIdx.x - d] : 0;
        __syncthreads();
        sm[threadIdx.x] += t;
        __syncthreads();
    }
    g_bsum[threadIdx.x] = sm[threadIdx.x] - v;
}

__global__ __launch_bounds__(256) void scan3_kernel(int N, int EP) {
    int i = blockIdx.x * 256 + threadIdx.x;
    if (i < N) { g_start[i] += g_bsum[i >> 8]; g_cur[i] = 0; }
    if (i == 0) g_start[N] = EP;
}

__global__ __launch_bounds__(256) void scatter_kernel(const int* __restrict__ ei, int E, int EP) {
    int e = blockIdx.x * blockDim.x + threadIdx.x;
    if (e >= EP) return;
    int s, dn;
    if (e < E) { s = ei[e]; dn = ei[E + e]; } else { s = dn = e - E; }
    int pos = atomicAdd(&g_cur[dn], 1);
    g_csrc[g_start[dn] + pos] = s;
}

// ---------------- node kernels: 8 nodes/warp ----------------
__global__ __launch_bounds__(128) void node_e_kernel(const float* __restrict__ x,
                                                     const float* __restrict__ b_lin,
                                                     const float* __restrict__ att,
                                                     int N) {
    __shared__ float sx[4][8][D_];
    int w = threadIdx.x >> 5, l = threadIdx.x & 31;
    int base = blockIdx.x * 32 + w * 8;
    if (base >= N) return;
#pragma unroll
    for (int j = 0; j < 8; j++) {
        int n = min(base + j, N - 1);
        ((float4*)sx[w][j])[l] = ((const float4*)x)[n * 32 + l];
    }
    __syncwarp();
    unsigned long long acc[8][2];
#pragma unroll
    for (int j = 0; j < 8; j++) { acc[j][0] = 0ull; acc[j][1] = 0ull; }
    const ulonglong2* Wt = (const ulonglong2*)g_WtE;
#pragma unroll 2
    for (int k = 0; k < D_; k++) {
        ulonglong2 wv = Wt[k * 32 + l];
#pragma unroll
        for (int j = 0; j < 8; j++) {
            unsigned long long ss = pack2(sx[w][j][k]);
            ffma2(acc[j][0], ss, wv.x);
            ffma2(acc[j][1], ss, wv.y);
        }
    }
    float4 bv = ((const float4*)b_lin)[l];
    int h = l >> 3, j0 = (l & 7) * 4;
    const float* at  = att + h * 64 + j0;
    const float* at2 = at + 32;
#pragma unroll
    for (int j = 0; j < 8; j++) {
        int n = base + j;
        if (n >= N) break;
        float4 a = unpack4(acc[j][0], acc[j][1]);
        a.x += bv.x; a.y += bv.y; a.z += bv.z; a.w += bv.w;
        ((float4*)g_xe)[n * 32 + l] = a;
        float pi = a.x * at[0]  + a.y * at[1]  + a.z * at[2]  + a.w * at[3];
        float pj = a.x * at2[0] + a.y * at2[1] + a.z * at2[2] + a.w * at2[3];
#pragma unroll
        for (int o = 4; o; o >>= 1) {
            pi += __shfl_down_sync(0xffffffffu, pi, o, 8);
            pj += __shfl_down_sync(0xffffffffu, pj, o, 8);
        }
        if ((l & 7) == 0) { g_ai[n * 4 + h] = pi; g_aj[n * 4 + h] = pj; }
    }
}

__global__ __launch_bounds__(128) void node_h_kernel(const float* __restrict__ x,
                                                     const float* __restrict__ b_lin,
                                                     const float* __restrict__ att,
                                                     int N) {
    __shared__ float sx[4][8][D_];
    int w = threadIdx.x >> 5, l = threadIdx.x & 31;
    int base = blockIdx.x * 32 + w * 8;
    if (base >= N) return;
    float pnx[8];
#pragma unroll
    for (int j = 0; j < 8; j++) {
        int n = min(base + j, N - 1);
        float4 xv = ((const float4*)x)[n * 32 + l];
        ((float4*)sx[w][j])[l] = xv;
        pnx[j] = d4(xv, xv);
    }
#pragma unroll
    for (int o = 16; o; o >>= 1) {
#pragma unroll
        for (int j = 0; j < 8; j++) pnx[j] += __shfl_xor_sync(0xffffffffu, pnx[j], o);
    }
    __syncwarp();
    unsigned long long acc[8][2];
#pragma unroll
    for (int j = 0; j < 8; j++) { acc[j][0] = 0ull; acc[j][1] = 0ull; }
    const ulonglong2* Wt = (const ulonglong2*)g_WtH;
#pragma unroll 2
    for (int k = 0; k < D_; k++) {
        ulonglong2 wv = Wt[k * 32 + l];
#pragma unroll
        for (int j = 0; j < 8; j++) {
            unsigned long long ss = pack2(sx[w][j][k]);
            ffma2(acc[j][0], ss, wv.x);
            ffma2(acc[j][1], ss, wv.y);
        }
    }
    float4 bvv = ((const float4*)b_lin)[l];
    float nb = fmaxf(sqrtf(wsum(d4(bvv, bvv))), MINNORM);
    float nhb = fminf(tanhf(nb), MAXN);
    float4 hb = f4s(bvv, nhb / nb);
    float y2 = nhb * nhb;

    float4 mx[8];
    float pm[8];
#pragma unroll
    for (int j = 0; j < 8; j++) {
        mx[j] = unpack4(acc[j][0], acc[j][1]);
        pm[j] = d4(mx[j], mx[j]);
    }
#pragma unroll
    for (int o = 16; o; o >>= 1) {
#pragma unroll
        for (int j = 0; j < 8; j++) pm[j] += __shfl_xor_sync(0xffffffffu, pm[j], o);
    }
    float nmv[8];
#pragma unroll
    for (int j = 0; j < 8; j++) {
        float n_x = fmaxf(sqrtf(pnx[j]), MINNORM);
        float n_mx = fmaxf(sqrtf(pm[j]), MINNORM);
        nmv[j] = fminf(tanhf(n_mx / n_x * atanhc(n_x)), MAXN);
        float s = nmv[j] / n_mx;
        mx[j] = f4s(mx[j], s);
    }
    float pxy[8];
#pragma unroll
    for (int j = 0; j < 8; j++) pxy[j] = d4(mx[j], hb);
#pragma unroll
    for (int o = 16; o; o >>= 1) {
#pragma unroll
        for (int j = 0; j < 8; j++) pxy[j] += __shfl_xor_sync(0xffffffffu, pxy[j], o);
    }

    int h = l >> 3, j0 = (l & 7) * 4;
    const float* at  = att + h * 64 + j0;
    const float* at2 = at + 32;
#pragma unroll
    for (int j = 0; j < 8; j++) {
        int n = base + j;
        if (n >= N) break;
        float x2 = nmv[j] * nmv[j];
        float xy = pxy[j];
        float A = 1.f + 2.f * xy + y2, B = 1.f - x2;
        float den = fmaxf(1.f + 2.f * xy + x2 * y2, MINNORM);
        float invden = 1.f / den;
        float nxh2 = fmaxf(A * A * x2 + 2.f * A * B * xy + B * B * y2, 0.f)
                     * invden * invden;
        float nxh = fmaxf(sqrtf(nxh2), MINNORM);
        float c = (nxh > MAXN) ? (MAXN / nxh) : 1.f;
        float4 xh = f4s(f4axby(A, mx[j], B, hb), invden * c);
        float nfin = c * nxh;
        float x2f = nfin * nfin;
        ((float4*)g_xh)[n * 32 + l] = xh;
        if (l == 0) g_x2[n] = x2f;
        float ncl = fmaxf(nfin, MINNORM);
        float4 lx = f4s(xh, atanhc(ncl) / ncl);
        ((float4*)g_lx)[n * 32 + l] = lx;
        float pi = lx.x * at[0]  + lx.y * at[1]  + lx.z * at[2]  + lx.w * at[3];
        float pj = lx.x * at2[0] + lx.y * at2[1] + lx.z * at2[2] + lx.w * at2[3];
#pragma unroll
        for (int o = 4; o; o >>= 1) {
            pi += __shfl_down_sync(0xffffffffu, pi, o, 8);
            pj += __shfl_down_sync(0xffffffffu, pj, o, 8);
        }
        if ((l & 7) == 0) { g_hi[n * 4 + h] = pi; g_hj[n * 4 + h] = pj; }
    }
}

// ---------------- fused edge (masked x4; algebraic exp-dist; fast exp) ----------------
__global__ __launch_bounds__(256) void fused_edge_kernel(const float* __restrict__ b_e,
                                                         const float* __restrict__ b_h,
                                                         const float* __restrict__ att_hf,
                                                         const float* __restrict__ att_ef,
                                                         float* __restrict__ out, int N) {
    int w = (blockIdx.x * blockDim.x + threadIdx.x) >> 5;
    int l = threadIdx.x & 31;
    if (w >= N) return;
    int dn = w;
    int beg = g_start[dn], end = g_start[dn + 1];
    int h = l >> 3;
    bool leader = (l & 7) == 0;

    float4 xd  = ((const float4*)g_xh)[dn * 32 + l];
    float  x2d = g_x2[dn];
    float  ai_l = g_ai[dn * 4 + h];
    float  hi_l = g_hi[dn * 4 + h];

    // ---- Pass A: distances + euclid softmax-weighted aggregation (masked x4) ----
    // exp(2*atanh(q)) == (1+q)/(1-q) for clamped q -> no transcendental needed.
    float sum_d = 0.f, sum_e = 0.f;
    float4 acc_e = make_float4(0.f, 0.f, 0.f, 0.f);
    for (int k = beg; k < end; k += 4) {
        int k1 = min(k + 1, end - 1), k2 = min(k + 2, end - 1), k3 = min(k + 3, end - 1);
        float m1 = (k + 1 < end) ? 1.f : 0.f;
        float m2 = (k + 2 < end) ? 1.f : 0.f;
        float m3 = (k + 3 < end) ? 1.f : 0.f;
        int s0 = g_csrc[k], s1 = g_csrc[k1], s2 = g_csrc[k2], s3 = g_csrc[k3];
        float4 v0 = ((const float4*)g_xh)[s0 * 32 + l];
        float4 v1 = ((const float4*)g_xh)[s1 * 32 + l];
        float4 v2 = ((const float4*)g_xh)[s2 * 32 + l];
        float4 v3 = ((const float4*)g_xh)[s3 * 32 + l];
        float4 e0 = ((const float4*)g_xe)[s0 * 32 + l];
        float4 e1 = ((const float4*)g_xe)[s1 * 32 + l];
        float4 e2 = ((const float4*)g_xe)[s2 * 32 + l];
        float4 e3 = ((const float4*)g_xe)[s3 * 32 + l];
        float le0 = __expf(lrelu(ai_l + g_aj[s0 * 4 + h]));
        float le1 = __expf(lrelu(ai_l + g_aj[s1 * 4 + h])) * m1;
        float le2 = __expf(lrelu(ai_l + g_aj[s2 * 4 + h])) * m2;
        float le3 = __expf(lrelu(ai_l + g_aj[s3 * 4 + h])) * m3;
        acc_e.x = fmaf(le0, e0.x, fmaf(le1, e1.x, fmaf(le2, e2.x, fmaf(le3, e3.x, acc_e.x))));
        acc_e.y = fmaf(le0, e0.y, fmaf(le1, e1.y, fmaf(le2, e2.y, fmaf(le3, e3.y, acc_e.y))));
        acc_e.z = fmaf(le0, e0.z, fmaf(le1, e1.z, fmaf(le2, e2.z, fmaf(le3, e3.z, acc_e.z))));
        acc_e.w = fmaf(le0, e0.w, fmaf(le1, e1.w, fmaf(le2, e2.w, fmaf(le3, e3.w, acc_e.w))));
        if (leader) sum_e += le0 + le1 + le2 + le3;
        float p0 = d4(xd, v0), p1 = d4(xd, v1), p2 = d4(xd, v2), p3 = d4(xd, v3);
#pragma unroll
        for (int o = 16; o; o >>= 1) {
            p0 += __shfl_xor_sync(0xffffffffu, p0, o);
            p1 += __shfl_xor_sync(0xffffffffu, p1, o);
            p2 += __shfl_xor_sync(0xffffffffu, p2, o);
            p3 += __shfl_xor_sync(0xffffffffu, p3, o);
        }
        if (l < 4 && k + l < end) {
            int ssel = (l == 0) ? s0 : (l == 1) ? s1 : (l == 2) ? s2 : s3;
            float pp = (l == 0) ? p0 : (l == 1) ? p1 : (l == 2) ? p2 : p3;
            float yy = g_x2[ssel];
            float A = 1.f - 2.f * pp + yy, B = 1.f - x2d;
            float den = fmaxf(1.f - 2.f * pp + x2d * yy, MINNORM);
            float num2 = fmaxf(A * A * x2d + B * B * yy - 2.f * A * B * pp, 0.f);
            float q = fminf(sqrtf(num2) / den, 1.0f - 1e-7f);
            float edd = (1.f + q) / (1.f - q);       // == exp(2*atanh(q))
            g_de[k + l] = edd;
            sum_d += edd;
        }
    }
    float inv_sd = 1.f / (wsum(sum_d) + 1e-16f);

    // ---- Pass B: hyperbolic softmax-weighted aggregation (masked x4) ----
    float sum_h = 0.f;
    float4 acc_h = make_float4(0.f, 0.f, 0.f, 0.f);
    for (int k = beg; k < end; k += 4) {
        int k1 = min(k + 1, end - 1), k2 = min(k + 2, end - 1), k3 = min(k + 3, end - 1);
        float m1 = (k + 1 < end) ? 1.f : 0.f;
        float m2 = (k + 2 < end) ? 1.f : 0.f;
        float m3 = (k + 3 < end) ? 1.f : 0.f;
        int s0 = g_csrc[k], s1 = g_csrc[k1], s2 = g_csrc[k2], s3 = g_csrc[k3];
        float4 l0 = ((const float4*)g_lx)[s0 * 32 + l];
        float4 l1 = ((const float4*)g_lx)[s1 * 32 + l];
        float4 l2 = ((const float4*)g_lx)[s2 * 32 + l];
        float4 l3 = ((const float4*)g_lx)[s3 * 32 + l];
        float d0 = g_de[k] * inv_sd,  d1 = g_de[k1] * inv_sd;
        float d2 = g_de[k2] * inv_sd, d3 = g_de[k3] * inv_sd;
        float a0 = __expf(lrelu((hi_l + g_hj[s0 * 4 + h]) * d0));
        float a1 = __expf(lrelu((hi_l + g_hj[s1 * 4 + h]) * d1)) * m1;
        float a2 = __expf(lrelu((hi_l + g_hj[s2 * 4 + h]) * d2)) * m2;
        float a3 = __expf(lrelu((hi_l + g_hj[s3 * 4 + h]) * d3)) * m3;
        acc_h.x = fmaf(a0, l0.x, fmaf(a1, l1.x, fmaf(a2, l2.x, fmaf(a3, l3.x, acc_h.x))));
        acc_h.y = fmaf(a0, l0.y, fmaf(a1, l1.y, fmaf(a2, l2.y, fmaf(a3, l3.y, acc_h.y))));
        acc_h.z = fmaf(a0, l0.z, fmaf(a1, l1.z, fmaf(a2, l2.z, fmaf(a3, l3.z, acc_h.z))));
        acc_h.w = fmaf(a0, l0.w, fmaf(a1, l1.w, fmaf(a2, l2.w, fmaf(a3, l3.w, acc_h.w))));
        if (leader) sum_h += a0 + a1 + a2 + a3;
    }

    float se = __shfl_sync(0xffffffffu, sum_e, h << 3);
    float sh = __shfl_sync(0xffffffffu, sum_h, h << 3);
    float inv_se = 1.f / (se + 1e-16f);
    float inv_sh = 1.f / (sh + 1e-16f);

    // ---- Finalize (scalar-norm algebra; 3 warp reductions) ----
    int n = dn;
    float4 be = ((const float4*)b_e)[l];
    float4 eo = make_float4(fmaxf(fmaf(acc_e.x, inv_se, be.x), 0.f),
                            fmaxf(fmaf(acc_e.y, inv_se, be.y), 0.f),
                            fmaxf(fmaf(acc_e.z, inv_se, be.z), 0.f),
                            fmaxf(fmaf(acc_e.w, inv_se, be.w), 0.f));
    float4 bh = ((const float4*)b_h)[l];
    float4 ot = make_float4(fmaxf(fmaf(acc_h.x, inv_sh, bh.x), 0.f),
                            fmaxf(fmaf(acc_h.y, inv_sh, bh.y), 0.f),
                            fmaxf(fmaf(acc_h.z, inv_sh, bh.z), 0.f),
                            fmaxf(fmaf(acc_h.w, inv_sh, bh.w), 0.f));
    float nt = fmaxf(sqrtf(wsum(d4(ot, ot))), MINNORM);
    float nho = fminf(tanhf(nt), MAXN);
    float4 ho = f4s(ot, nho / nt);
    float x2 = nho * nho;
    float ne2 = wsum(d4(eo, eo));
    float ne = fmaxf(sqrtf(ne2), MINNORM);
    float nye = fminf(tanhf(ne), MAXN);
    float4 ye = f4s(eo, nye / ne);
    float y2 = nye * nye;
    float xy = wsum(d4(ho, ye));
    float A = 1.f - 2.f * xy + y2, B = 1.f - x2;
    float den = fmaxf(1.f - 2.f * xy + x2 * y2, MINNORM);
    float num2 = fmaxf(A * A * x2 + B * B * y2 - 2.f * A * B * xy, 0.f);
    float r = 2.f * atanhc(sqrtf(num2) / den) * att_hf[0];
    float ny = fmaxf(nye, MINNORM);
    float t3 = tanhf(r * atanhc(ny));
    float kxe = t3 / ny;
    float nxe2 = fabsf(kxe) * nye;
    float c2 = (nxe2 > MAXN) ? (MAXN / fmaxf(nxe2, MINNORM)) : 1.f;
    float kxe2 = kxe * c2;
    float4 xe2 = f4s(ye, kxe2);
    float nxe2c = nxe2 * c2;
    float y2b = nxe2c * nxe2c;
    float xyb = xy * kxe2;
    float A2 = 1.f + 2.f * xyb + y2b, B2 = 1.f - x2;
    float den2 = fmaxf(1.f + 2.f * xyb + x2 * y2b, MINNORM);
    float invden2 = 1.f / den2;
    float nhf2 = fmaxf(A2 * A2 * x2 + 2.f * A2 * B2 * xyb + B2 * B2 * y2b, 0.f)
                 * invden2 * invden2;
    float nhf = fmaxf(sqrtf(nhf2), MINNORM);
    float c3 = (nhf > MAXN) ? (MAXN / nhf) : 1.f;
    float4 hf = f4s(f4axby(A2, ho, B2, xe2), invden2 * c3);
    float nclh = fmaxf(nho, MINNORM);
    float alh = atanhc(nclh);
    float kl = alh / nclh;
    float4 lh = f4s(ho, kl);
    float dot_ho_eo = xy * ne / nye;
    float de = (alh * alh - 2.f * kl * dot_ho_eo + ne2) * att_ef[0];
    float4 ef = make_float4(eo.x + de * lh.x, eo.y + de * lh.y,
                            eo.z + de * lh.z, eo.w + de * lh.w);
    ((float4*)out)[n * 32 + l] = hf;
    ((float4*)out)[(size_t)N * 32 + n * 32 + l] = ef;
}

// ---------------- launch: node_e / node_h / CSR on three concurrent streams ----------------
extern "C" void kernel_launch(void* const* d_in, const int* in_sizes, int n_in,
                              void* d_out, int out_size) {
    const float* x_e      = (const float*)d_in[0];
    const float* x_h      = (const float*)d_in[1];
    const int*   ei       = (const int*)d_in[2];
    const float* W_e      = (const float*)d_in[3];
    const float* b_lin_e  = (const float*)d_in[4];
    const float* att_e    = (const float*)d_in[5];
    const float* b_e      = (const float*)d_in[6];
    const float* W_h      = (const float*)d_in[7];
    const float* b_lin_h  = (const float*)d_in[8];
    const float* att_h    = (const float*)d_in[9];
    const float* b_h      = (const float*)d_in[10];
    const float* att_hf   = (const float*)d_in[11];
    const float* att_ef   = (const float*)d_in[12];
    float* out = (float*)d_out;

    int N  = in_sizes[0] / D_;
    int E  = in_sizes[2] / 2;
    int EP = E + N;
    int nsb = (N + 255) / 256;
    int ninit = (N > 2 * D_ * D_) ? N : 2 * D_ * D_;

    static cudaStream_t s2 = nullptr, s3 = nullptr;
    static cudaEvent_t evFork = nullptr, evJoin2 = nullptr, evJoin3 = nullptr;
    if (s2 == nullptr) {
        cudaStreamCreateWithFlags(&s2, cudaStreamNonBlocking);
        cudaStreamCreateWithFlags(&s3, cudaStreamNonBlocking);
        cudaEventCreateWithFlags(&evFork, cudaEventDisableTiming);
        cudaEventCreateWithFlags(&evJoin2, cudaEventDisableTiming);
        cudaEventCreateWithFlags(&evJoin3, cudaEventDisableTiming);
    }

    // main stream: init (weights + deg zero)
    init_kernel<<<(ninit + 255) / 256, 256>>>(W_e, W_h, N);
    cudaEventRecord(evFork, 0);

    // side stream s2: CSR build chain
    cudaStreamWaitEvent(s2, evFork, 0);
    count_kernel<<<(EP + 255) / 256, 256, 0, s2>>>(ei, E, EP);
    scan1_kernel<<<nsb, 256, 0, s2>>>(N);
    scan2_kernel<<<1, 256, 0, s2>>>(nsb);
    scan3_kernel<<<(N + 255) / 256, 256, 0, s2>>>(N, EP);
    scatter_kernel<<<(EP + 255) / 256, 256, 0, s2>>>(ei, E, EP);
    cudaEventRecord(evJoin2, s2);

    // side stream s3: hyperbolic node kernel (concurrent with node_e)
    cudaStreamWaitEvent(s3, evFork, 0);
    node_h_kernel<<<(N + 31) / 32, 128, 0, s3>>>(x_h, b_lin_h, att_h, N);
    cudaEventRecord(evJoin3, s3);

    // main stream: euclidean node kernel
    node_e_kernel<<<(N + 31) / 32, 128>>>(x_e, b_lin_e, att_e, N);

    // join all, then fused edge + finalize
    cudaStreamWaitEvent(0, evJoin2, 0);
    cudaStreamWaitEvent(0, evJoin3, 0);
    fused_edge_kernel<<<(N * 32 + 255) / 256, 256>>>(b_e, b_h, att_hf, att_ef, out, N);
}